// round 14
// baseline (speedup 1.0000x reference)
#include <cuda_runtime.h>
#include <cuda_fp16.h>
#include <math.h>
#include <stdint.h>

#define EMBED 1024
#define NQV   1024
#define NKV   2048
#define BATCH 4
#define NH    16
#define HD    64

// ---------------------------------------------------------------------------
// Scratch (__device__ globals — allocation-free rule)
// ---------------------------------------------------------------------------
__device__ float g_lb[BATCH * NKV];

__device__ __half g_q16[BATCH * NQV * EMBED];                         // single
__device__ __half g_k16[BATCH * NKV * EMBED];                         // single
__device__ __half g_v16h[BATCH * NKV * EMBED], g_v16l[BATCH * NKV * EMBED];
__device__ __half g_wq16[EMBED * EMBED], g_wk16[EMBED * EMBED];
__device__ __half g_wv16[EMBED * EMBED], g_wo16[EMBED * EMBED];
__device__ __half g_qs16[BATCH * NQV * EMBED];                        // single, prescaled
__device__ __half g_ks16[BATCH * NKV * EMBED];                        // single
__device__ __half g_vt16[BATCH * NH * HD * NKV];
__device__ __half g_ao16h[BATCH * NQV * EMBED], g_ao16l[BATCH * NQV * EMBED];

// ---------------------------------------------------------------------------
// PTX helpers (sm_80-compatible ISA: compute_103 has no 'a' features)
// ---------------------------------------------------------------------------
__device__ __forceinline__ uint32_t smem_u32(const void* p) {
    uint32_t a;
    asm("{ .reg .u64 t; cvta.to.shared.u64 t, %1; cvt.u32.u64 %0, t; }"
        : "=r"(a) : "l"(p));
    return a;
}
__device__ __forceinline__ void cp16(uint32_t dst, const void* src) {
    asm volatile("cp.async.cg.shared.global [%0], [%1], 16;"
                 :: "r"(dst), "l"(src) : "memory");
}
#define CP_COMMIT() asm volatile("cp.async.commit_group;" ::: "memory")
#define CP_WAIT(n)  asm volatile("cp.async.wait_group %0;" :: "n"(n) : "memory")

__device__ __forceinline__ void ldsm4(uint32_t* r, uint32_t addr) {
    asm volatile("ldmatrix.sync.aligned.m8n8.x4.shared.b16 {%0,%1,%2,%3}, [%4];"
                 : "=r"(r[0]), "=r"(r[1]), "=r"(r[2]), "=r"(r[3]) : "r"(addr));
}
__device__ __forceinline__ void mma_h(float* c, const uint32_t* a,
                                      uint32_t b0, uint32_t b1) {
    asm volatile(
        "mma.sync.aligned.m16n8k16.row.col.f32.f16.f16.f32 "
        "{%0,%1,%2,%3}, {%4,%5,%6,%7}, {%8,%9}, {%0,%1,%2,%3};"
        : "+f"(c[0]), "+f"(c[1]), "+f"(c[2]), "+f"(c[3])
        : "r"(a[0]), "r"(a[1]), "r"(a[2]), "r"(a[3]), "r"(b0), "r"(b1));
}
__device__ __forceinline__ uint32_t packh(float lo, float hi) {
    __half2 v = __floats2half2_rn(lo, hi);
    return *(uint32_t*)&v;
}

// ---------------------------------------------------------------------------
// merged conversions: q single | k single | v hi/lo
// ---------------------------------------------------------------------------
__global__ __launch_bounds__(256) void cvt_inputs(
    const float* __restrict__ q, const float* __restrict__ k,
    const float* __restrict__ v,
    __half* __restrict__ q16, __half* __restrict__ k16,
    __half* __restrict__ vh, __half* __restrict__ vl)
{
    const int gid = blockIdx.x * 256 + threadIdx.x;
    if (gid < (3 << 20)) {
        const float* src = (gid < (1 << 20)) ? q : k;
        __half* dst = (gid < (1 << 20)) ? q16 : k16;
        const int idx = ((gid < (1 << 20)) ? gid : gid - (1 << 20)) * 4;
        float4 x = *(const float4*)(src + idx);
        *(__half2*)(dst + idx)     = __floats2half2_rn(x.x, x.y);
        *(__half2*)(dst + idx + 2) = __floats2half2_rn(x.z, x.w);
    } else {
        const int idx = (gid - (3 << 20)) * 4;
        float4 x = *(const float4*)(v + idx);
        __half h0 = __float2half_rn(x.x), h1 = __float2half_rn(x.y);
        __half h2 = __float2half_rn(x.z), h3 = __float2half_rn(x.w);
        *(__half2*)(vh + idx)     = __half2(h0, h1);
        *(__half2*)(vh + idx + 2) = __half2(h2, h3);
        *(__half2*)(vl + idx) = __half2(__float2half_rn(x.x - __half2float(h0)),
                                        __float2half_rn(x.y - __half2float(h1)));
        *(__half2*)(vl + idx + 2) = __half2(__float2half_rn(x.z - __half2float(h2)),
                                            __float2half_rn(x.w - __half2float(h3)));
    }
}

__global__ __launch_bounds__(256) void cvt_weights(
    const float* __restrict__ w0, const float* __restrict__ w1,
    const float* __restrict__ w2, const float* __restrict__ w3,
    __half* __restrict__ o0, __half* __restrict__ o1,
    __half* __restrict__ o2, __half* __restrict__ o3)
{
    const int gid = blockIdx.x * 256 + threadIdx.x;
    const int seg = gid >> 18;
    const int idx = (gid & 262143) * 4;
    const float* src = (seg == 0) ? w0 : (seg == 1) ? w1 : (seg == 2) ? w2 : w3;
    __half* dst = (seg == 0) ? o0 : (seg == 1) ? o1 : (seg == 2) ? o2 : o3;
    float4 x = *(const float4*)(src + idx);
    *(__half2*)(dst + idx)     = __floats2half2_rn(x.x, x.y);
    *(__half2*)(dst + idx + 2) = __floats2half2_rn(x.z, x.w);
}

__global__ __launch_bounds__(256) void log_mult(const float* __restrict__ m,
                                                float* __restrict__ lb) {
    int i = blockIdx.x * 256 + threadIdx.x;
    lb[i] = __logf(m[i]);
}

// ---------------------------------------------------------------------------
// fp16 HMMA GEMM: C = (Ah [+ Al]) B^T + bias
// Block 128x256, 8 warps 64x64, k-tile 32, 3 stages (round-11 shape).
// TWOTERM: 1 -> A = Ah + Al (2 MMA terms); 0 -> A = Ah only.
// MODE 0: fp32 out; MODE 3: transposed fp16 V^T [b][h][d][key];
// MODE 5: fp16 single out; MODE 6: fp16 single out scaled 0.125
// ---------------------------------------------------------------------------
#define ROWB   80
#define A_MATB (128 * ROWB)
#define B_MATB (256 * ROWB)
#define F2_STG  (2 * A_MATB + B_MATB)      // 40960
#define F2_SMEM (3 * F2_STG)               // 122880

template<int MODE, int TWOTERM>
__global__ __launch_bounds__(256) void gemm_f2(
    const __half* __restrict__ Ah, const __half* __restrict__ Al,
    const __half* __restrict__ Bh, const float* __restrict__ bias,
    float* __restrict__ C, __half* __restrict__ VT,
    __half* __restrict__ Oh,
    int M, int N, int K)
{
    extern __shared__ __align__(1024) char sm[];
    const uint32_t sb = smem_u32(sm);
    const int tid = threadIdx.x;
    const int lane = tid & 31, wid = tid >> 5;
    const int warp_m = wid >> 2, warp_n = wid & 3;
    const int bm = blockIdx.y * 128, bn = blockIdx.x * 256;

    const int lrw = tid >> 1;
    const int lck = (tid & 1) * 2;
    const __half* gAh = Ah + (size_t)(bm + lrw) * K + lck * 8;
    const __half* gAl = TWOTERM ? (Al + (size_t)(bm + lrw) * K + lck * 8) : nullptr;
    const __half* gBh0 = Bh + (size_t)(bn + lrw) * K + lck * 8;
    const __half* gBh1 = gBh0 + (size_t)128 * K;
    const uint32_t dA  = lrw * ROWB + lck * 16;
    const uint32_t dB0 = 2 * A_MATB + lrw * ROWB + lck * 16;
    const uint32_t dB1 = dB0 + 128 * ROWB;

    const int NKT = K / 32;

#define ISSUE(s, kt) do {                                                   \
        const uint32_t so = sb + (s) * F2_STG;                              \
        const size_t go = (size_t)(kt) * 32;                                \
        cp16(so + dA,               gAh + go);                              \
        cp16(so + dA + 16,          gAh + go + 8);                          \
        if (TWOTERM) {                                                      \
            cp16(so + dA + A_MATB,      gAl + go);                          \
            cp16(so + dA + A_MATB + 16, gAl + go + 8);                      \
        }                                                                   \
        cp16(so + dB0,              gBh0 + go);                             \
        cp16(so + dB0 + 16,         gBh0 + go + 8);                         \
        cp16(so + dB1,              gBh1 + go);                             \
        cp16(so + dB1 + 16,         gBh1 + go + 8);                         \
        CP_COMMIT();                                                       \
    } while (0)

    ISSUE(0, 0);
    ISSUE(1, 1);

    float c[4][8][4];
#pragma unroll
    for (int i = 0; i < 4; i++)
#pragma unroll
        for (int j = 0; j < 8; j++)
#pragma unroll
            for (int q = 0; q < 4; q++) c[i][j][q] = 0.f;

    const uint32_t frow = lane & 15;
    const uint32_t fkb  = ((lane >> 4) & 1) * 16;
    const uint32_t aBase = (warp_m * 64 + frow) * ROWB + fkb;
    const uint32_t bBase = 2 * A_MATB + (warp_n * 64 + frow) * ROWB + fkb;

#pragma unroll 1
    for (int kt = 0; kt < NKT; kt++) {
        if (kt + 1 < NKT) { CP_WAIT(1); } else { CP_WAIT(0); }
        __syncthreads();
        if (kt + 2 < NKT) ISSUE((kt + 2) % 3, kt + 2);
        const uint32_t st = sb + (kt % 3) * F2_STG;

#pragma unroll
        for (int ks = 0; ks < 2; ks++) {
            const uint32_t ko = ks * 32;
            uint32_t ah[4][4], al_[4][4];
#pragma unroll
            for (int mi = 0; mi < 4; mi++) {
                ldsm4(ah[mi], st + aBase + mi * 16 * ROWB + ko);
                if (TWOTERM)
                    ldsm4(al_[mi], st + A_MATB + aBase + mi * 16 * ROWB + ko);
            }
#pragma unroll
            for (int nb = 0; nb < 4; nb++) {
                uint32_t bh[4];
                ldsm4(bh, st + bBase + nb * 16 * ROWB + ko);
#pragma unroll
                for (int mi = 0; mi < 4; mi++) {
                    mma_h(c[mi][nb * 2],     ah[mi], bh[0], bh[2]);
                    mma_h(c[mi][nb * 2 + 1], ah[mi], bh[1], bh[3]);
                    if (TWOTERM) {
                        mma_h(c[mi][nb * 2],     al_[mi], bh[0], bh[2]);
                        mma_h(c[mi][nb * 2 + 1], al_[mi], bh[1], bh[3]);
                    }
                }
            }
        }
    }

    const int erow = lane >> 2, ecol = (lane & 3) * 2;
#pragma unroll
    for (int mi = 0; mi < 4; mi++) {
        const int r0 = bm + warp_m * 64 + mi * 16 + erow;
#pragma unroll
        for (int n8 = 0; n8 < 8; n8++) {
            const int cc = bn + warp_n * 64 + n8 * 8 + ecol;
            const float b0 = bias[cc], b1 = bias[cc + 1];
            if (MODE == 0) {
                float2 v0 = {c[mi][n8][0] + b0, c[mi][n8][1] + b1};
                float2 v1 = {c[mi][n8][2] + b0, c[mi][n8][3] + b1};
                *(float2*)(C + (size_t)r0 * N + cc)       = v0;
                *(float2*)(C + (size_t)(r0 + 8) * N + cc) = v1;
            } else if (MODE == 3) {
#pragma unroll
                for (int rr = 0; rr < 2; rr++) {
                    const int r = r0 + rr * 8;
                    const int bb = r >> 11, key = r & (NKV - 1);
                    const float v0 = c[mi][n8][rr * 2]     + b0;
                    const float v1 = c[mi][n8][rr * 2 + 1] + b1;
                    const size_t o0 = ((size_t)((bb * NH + (cc >> 6)) * HD + (cc & 63))) * NKV + key;
                    const size_t o1 = ((size_t)((bb * NH + ((cc + 1) >> 6)) * HD + ((cc + 1) & 63))) * NKV + key;
                    VT[o0] = __float2half_rn(v0);
                    VT[o1] = __float2half_rn(v1);
                }
            } else {
                const float sc = (MODE == 6) ? 0.125f : 1.0f;
                size_t i0 = (size_t)r0 * N + cc, i1 = (size_t)(r0 + 8) * N + cc;
                *(uint32_t*)(Oh + i0) = packh((c[mi][n8][0] + b0) * sc,
                                              (c[mi][n8][1] + b1) * sc);
                *(uint32_t*)(Oh + i1) = packh((c[mi][n8][2] + b0) * sc,
                                              (c[mi][n8][3] + b1) * sc);
            }
        }
    }
#undef ISSUE
}

// ---------------------------------------------------------------------------
// fp16 HMMA flash attention (single-term): S = Q K^T + log m; O = P V
// Epilogue writes fp16 hi/lo for the 2-term O projection.
// ---------------------------------------------------------------------------
#define QROW 144
#define SQ_SZ  (128 * QROW)               // 18432 (single Q plane)
#define SV     (64 * QROW)                // 9216
#define SLB    (2 * 64 * QROW)            // 18432
#define STG_SZ (2 * 64 * QROW + 256)      // 18688
#define ASMEM  (SQ_SZ + 3 * STG_SZ)       // 74496

__global__ __launch_bounds__(256) void attn_hmma(
    const __half* __restrict__ Qf, const __half* __restrict__ Kf,
    const __half* __restrict__ VT, const float* __restrict__ lbG,
    __half* __restrict__ Oh, __half* __restrict__ Ol)
{
    extern __shared__ __align__(1024) char sm[];
    const uint32_t sb = smem_u32(sm);
    const int qt = blockIdx.x, h = blockIdx.y, b = blockIdx.z;
    const int tid = threadIdx.x;
    const int lane = tid & 31, wid = tid >> 5;

    // Q tile via cp.async (pre-scaled, single fp16)
    {
        const int row = tid >> 1;
        const int co = (tid & 1) * 32;
        const __half* gq = Qf + ((size_t)(b * NQV + qt * 128 + row)) * EMBED + h * HD + co;
        const uint32_t dq = sb + row * QROW + co * 2;
#pragma unroll
        for (int i = 0; i < 4; i++) cp16(dq + i * 16, gq + i * 8);
    }

    const int srow = tid >> 2, scq = tid & 3;
    const __half* gK = Kf + ((size_t)(b * NKV + srow)) * EMBED + h * HD + scq * 16;
    const __half* gV = VT + ((size_t)((b * NH + h) * HD + srow)) * NKV + scq * 16;
    const uint32_t sdst = srow * QROW + scq * 32;
    const float* gLB = lbG + (size_t)b * NKV;

#define AISSUE(s, kt) do {                                                  \
        const uint32_t so = sb + SQ_SZ + (s) * STG_SZ;                      \
        const size_t koK = (size_t)(kt) * 64 * EMBED;                       \
        const size_t koV = (size_t)(kt) * 64;                               \
        cp16(so + sdst,           gK + koK);                                \
        cp16(so + sdst + 16,      gK + koK + 8);                            \
        cp16(so + SV + sdst,      gV + koV);                                \
        cp16(so + SV + sdst + 16, gV + koV + 8);                            \
        if (tid < 16) cp16(so + SLB + tid * 16, gLB + (kt) * 64 + tid * 4); \
        CP_COMMIT();                                                       \
    } while (0)

    AISSUE(0, 0);   // Q joins group 0
    AISSUE(1, 1);

    const uint32_t frow = lane & 15;
    const uint32_t fkb  = ((lane >> 4) & 1) * 16;
    const uint32_t qBase = (wid * 16 + frow) * QROW + fkb;
    uint32_t qhf[4][4];

    float o[8][4];
#pragma unroll
    for (int j = 0; j < 8; j++)
#pragma unroll
        for (int q = 0; q < 4; q++) o[j][q] = 0.f;
    float m0 = -1e30f, m1 = -1e30f, l0 = 0.f, l1 = 0.f;

    const int NT = NKV / 64;
#pragma unroll 1
    for (int kt = 0; kt < NT; kt++) {
        if (kt + 1 < NT) { CP_WAIT(1); } else { CP_WAIT(0); }
        __syncthreads();
        if (kt == 0) {
#pragma unroll
            for (int ks = 0; ks < 4; ks++) ldsm4(qhf[ks], sb + qBase + ks * 32);
        }
        if (kt + 2 < NT) AISSUE((kt + 2) % 3, kt + 2);
        const uint32_t st = sb + SQ_SZ + (kt % 3) * STG_SZ;

        // S = Q K^T (single term)
        float c[8][4];
#pragma unroll
        for (int j = 0; j < 8; j++)
#pragma unroll
            for (int q = 0; q < 4; q++) c[j][q] = 0.f;

#pragma unroll
        for (int ks = 0; ks < 4; ks++) {
#pragma unroll
            for (int nb = 0; nb < 4; nb++) {
                uint32_t kf[4];
                ldsm4(kf, st + (nb * 16 + frow) * QROW + fkb + ks * 32);
                mma_h(c[nb * 2],     qhf[ks], kf[0], kf[2]);
                mma_h(c[nb * 2 + 1], qhf[ks], kf[1], kf[3]);
            }
        }

        // + log multiplicity
        const float* lbs = (const float*)(sm + SQ_SZ + (kt % 3) * STG_SZ + SLB);
#pragma unroll
        for (int j = 0; j < 8; j++) {
            float2 lb2 = *(const float2*)(lbs + j * 8 + (lane & 3) * 2);
            c[j][0] += lb2.x; c[j][1] += lb2.y;
            c[j][2] += lb2.x; c[j][3] += lb2.y;
        }

        // online softmax
        float rm0 = -1e30f, rm1 = -1e30f;
#pragma unroll
        for (int j = 0; j < 8; j++) {
            rm0 = fmaxf(rm0, fmaxf(c[j][0], c[j][1]));
            rm1 = fmaxf(rm1, fmaxf(c[j][2], c[j][3]));
        }
#pragma unroll
        for (int off = 1; off < 4; off <<= 1) {
            rm0 = fmaxf(rm0, __shfl_xor_sync(0xffffffffu, rm0, off));
            rm1 = fmaxf(rm1, __shfl_xor_sync(0xffffffffu, rm1, off));
        }
        const float mn0 = fmaxf(m0, rm0), mn1 = fmaxf(m1, rm1);
        const float al0 = __expf(m0 - mn0), al1 = __expf(m1 - mn1);
        float rs0 = 0.f, rs1 = 0.f;
#pragma unroll
        for (int j = 0; j < 8; j++) {
            c[j][0] = __expf(c[j][0] - mn0); rs0 += c[j][0];
            c[j][1] = __expf(c[j][1] - mn0); rs0 += c[j][1];
            c[j][2] = __expf(c[j][2] - mn1); rs1 += c[j][2];
            c[j][3] = __expf(c[j][3] - mn1); rs1 += c[j][3];
        }
#pragma unroll
        for (int off = 1; off < 4; off <<= 1) {
            rs0 += __shfl_xor_sync(0xffffffffu, rs0, off);
            rs1 += __shfl_xor_sync(0xffffffffu, rs1, off);
        }
        l0 = l0 * al0 + rs0;  m0 = mn0;
        l1 = l1 * al1 + rs1;  m1 = mn1;
#pragma unroll
        for (int j = 0; j < 8; j++) {
            o[j][0] *= al0; o[j][1] *= al0;
            o[j][2] *= al1; o[j][3] *= al1;
        }

        // O += P V (single term)
#pragma unroll
        for (int kk = 0; kk < 4; kk++) {
            const int j0 = 2 * kk, j1 = 2 * kk + 1;
            uint32_t ah[4];
            ah[0] = packh(c[j0][0], c[j0][1]);
            ah[1] = packh(c[j0][2], c[j0][3]);
            ah[2] = packh(c[j1][0], c[j1][1]);
            ah[3] = packh(c[j1][2], c[j1][3]);
#pragma unroll
            for (int nb = 0; nb < 4; nb++) {
                uint32_t vh[4];
                ldsm4(vh, st + SV + (nb * 16 + frow) * QROW + fkb + kk * 32);
                mma_h(o[nb * 2],     ah, vh[0], vh[2]);
                mma_h(o[nb * 2 + 1], ah, vh[1], vh[3]);
            }
        }
    }

    // epilogue: normalize, write fp16 hi/lo (for 2-term O projection)
    const float inv0 = 1.f / l0, inv1 = 1.f / l1;
    const int r0 = qt * 128 + wid * 16 + (lane >> 2);
    const int cc0 = h * HD + (lane & 3) * 2;
#pragma unroll
    for (int j = 0; j < 8; j++) {
        const int col = cc0 + j * 8;
        {
            float v0 = o[j][0] * inv0, v1 = o[j][1] * inv0;
            float h0 = __half2float(__float2half_rn(v0));
            float h1 = __half2float(__float2half_rn(v1));
            size_t idx = ((size_t)(b * NQV + r0)) * EMBED + col;
            *(uint32_t*)(Oh + idx) = packh(h0, h1);
            *(uint32_t*)(Ol + idx) = packh(v0 - h0, v1 - h1);
        }
        {
            float v0 = o[j][2] * inv1, v1 = o[j][3] * inv1;
            float h0 = __half2float(__float2half_rn(v0));
            float h1 = __half2float(__float2half_rn(v1));
            size_t idx = ((size_t)(b * NQV + r0 + 8)) * EMBED + col;
            *(uint32_t*)(Oh + idx) = packh(h0, h1);
            *(uint32_t*)(Ol + idx) = packh(v0 - h0, v1 - h1);
        }
    }
#undef AISSUE
}

// ---------------------------------------------------------------------------
extern "C" void kernel_launch(void* const* d_in, const int* in_sizes, int n_in,
                              void* d_out, int out_size)
{
    const float* query = (const float*)d_in[0];
    const float* key   = (const float*)d_in[1];
    const float* value = (const float*)d_in[2];
    const float* mult  = (const float*)d_in[3];
    const float* wq_w  = (const float*)d_in[4];
    const float* wq_b  = (const float*)d_in[5];
    const float* wk_w  = (const float*)d_in[6];
    const float* wk_b  = (const float*)d_in[7];
    const float* wv_w  = (const float*)d_in[8];
    const float* wv_b  = (const float*)d_in[9];
    const float* wo_w  = (const float*)d_in[10];
    const float* wo_b  = (const float*)d_in[11];
    float* out = (float*)d_out;

    float* glb;  cudaGetSymbolAddress((void**)&glb, g_lb);
    __half *q16,*k16,*v16h,*v16l;
    __half *wq16,*wk16,*wv16,*wo16;
    __half *qs16,*ks16,*vt16,*ao16h,*ao16l;
    cudaGetSymbolAddress((void**)&q16, g_q16);
    cudaGetSymbolAddress((void**)&k16, g_k16);
    cudaGetSymbolAddress((void**)&v16h, g_v16h); cudaGetSymbolAddress((void**)&v16l, g_v16l);
    cudaGetSymbolAddress((void**)&wq16, g_wq16); cudaGetSymbolAddress((void**)&wk16, g_wk16);
    cudaGetSymbolAddress((void**)&wv16, g_wv16); cudaGetSymbolAddress((void**)&wo16, g_wo16);
    cudaGetSymbolAddress((void**)&qs16, g_qs16);
    cudaGetSymbolAddress((void**)&ks16, g_ks16);
    cudaGetSymbolAddress((void**)&vt16, g_vt16);
    cudaGetSymbolAddress((void**)&ao16h, g_ao16h); cudaGetSymbolAddress((void**)&ao16l, g_ao16l);

    cudaFuncSetAttribute((void*)gemm_f2<0,1>, cudaFuncAttributeMaxDynamicSharedMemorySize, F2_SMEM);
    cudaFuncSetAttribute((void*)gemm_f2<3,1>, cudaFuncAttributeMaxDynamicSharedMemorySize, F2_SMEM);
    cudaFuncSetAttribute((void*)gemm_f2<5,0>, cudaFuncAttributeMaxDynamicSharedMemorySize, F2_SMEM);
    cudaFuncSetAttribute((void*)gemm_f2<6,0>, cudaFuncAttributeMaxDynamicSharedMemorySize, F2_SMEM);
    cudaFuncSetAttribute(attn_hmma, cudaFuncAttributeMaxDynamicSharedMemorySize, ASMEM);

    const int MQ = BATCH * NQV;   // 4096
    const int MK = BATCH * NKV;   // 8192

    // 0: inputs -> fp16 (q,k single; v hi/lo)
    cvt_inputs<<<20480, 256>>>(query, key, value, q16, k16, v16h, v16l);
    // 1: weights -> fp16
    cvt_weights<<<4096, 256>>>(wq_w, wk_w, wv_w, wo_w, wq16, wk16, wv16, wo16);
    // 2: log multiplicities
    log_mult<<<MK / 256, 256>>>(mult, glb);
    // 3: Q proj (single-A) -> scaled fp16 single
    gemm_f2<6,0><<<dim3(EMBED / 256, MQ / 128), 256, F2_SMEM>>>(
        q16, nullptr, wq16, wq_b, nullptr, nullptr, qs16, MQ, EMBED, EMBED);
    // 4: K proj (single-A) -> fp16 single
    gemm_f2<5,0><<<dim3(EMBED / 256, MK / 128), 256, F2_SMEM>>>(
        k16, nullptr, wk16, wk_b, nullptr, nullptr, ks16, MK, EMBED, EMBED);
    // 5 (ncu): V proj (2-term) -> transposed fp16 V^T
    gemm_f2<3,1><<<dim3(EMBED / 256, MK / 128), 256, F2_SMEM>>>(
        v16h, v16l, wv16, wv_b, nullptr, vt16, nullptr, MK, EMBED, EMBED);
    // 6: attention (single-term QK, PV)
    attn_hmma<<<dim3(NQV / 128, NH, BATCH), 256, ASMEM>>>(
        qs16, ks16, vt16, glb, ao16h, ao16l);
    // 7: O proj (2-term) -> fp32 out
    gemm_f2<0,1><<<dim3(EMBED / 256, MQ / 128), 256, F2_SMEM>>>(
        ao16h, ao16l, wo16, wo_b, out, nullptr, nullptr, MQ, EMBED, EMBED);
}

// round 15
// speedup vs baseline: 1.0060x; 1.0060x over previous
#include <cuda_runtime.h>
#include <cuda_fp16.h>
#include <math.h>
#include <stdint.h>

#define EMBED 1024
#define NQV   1024
#define NKV   2048
#define BATCH 4
#define NH    16
#define HD    64

// ---------------------------------------------------------------------------
// Scratch (__device__ globals — allocation-free rule)
// ---------------------------------------------------------------------------
__device__ float g_lb[BATCH * NKV];

__device__ __half g_q16[BATCH * NQV * EMBED];
__device__ __half g_k16[BATCH * NKV * EMBED];
__device__ __half g_v16h[BATCH * NKV * EMBED], g_v16l[BATCH * NKV * EMBED];
__device__ __half g_wq16[EMBED * EMBED], g_wk16[EMBED * EMBED];
__device__ __half g_wv16[EMBED * EMBED], g_wo16[EMBED * EMBED];
__device__ __half g_qs16[BATCH * NQV * EMBED];      // prescaled
__device__ __half g_ks16[BATCH * NKV * EMBED];
__device__ __half g_vt16[BATCH * NH * HD * NKV];
__device__ __half g_ao16h[BATCH * NQV * EMBED], g_ao16l[BATCH * NQV * EMBED];

// ---------------------------------------------------------------------------
// PTX helpers (sm_80-compatible ISA: compute_103 has no 'a' features)
// ---------------------------------------------------------------------------
__device__ __forceinline__ uint32_t smem_u32(const void* p) {
    uint32_t a;
    asm("{ .reg .u64 t; cvta.to.shared.u64 t, %1; cvt.u32.u64 %0, t; }"
        : "=r"(a) : "l"(p));
    return a;
}
__device__ __forceinline__ void cp16(uint32_t dst, const void* src) {
    asm volatile("cp.async.cg.shared.global [%0], [%1], 16;"
                 :: "r"(dst), "l"(src) : "memory");
}
#define CP_COMMIT() asm volatile("cp.async.commit_group;" ::: "memory")
#define CP_WAIT(n)  asm volatile("cp.async.wait_group %0;" :: "n"(n) : "memory")

__device__ __forceinline__ void ldsm4(uint32_t* r, uint32_t addr) {
    asm volatile("ldmatrix.sync.aligned.m8n8.x4.shared.b16 {%0,%1,%2,%3}, [%4];"
                 : "=r"(r[0]), "=r"(r[1]), "=r"(r[2]), "=r"(r[3]) : "r"(addr));
}
__device__ __forceinline__ void mma_h(float* c, const uint32_t* a,
                                      uint32_t b0, uint32_t b1) {
    asm volatile(
        "mma.sync.aligned.m16n8k16.row.col.f32.f16.f16.f32 "
        "{%0,%1,%2,%3}, {%4,%5,%6,%7}, {%8,%9}, {%0,%1,%2,%3};"
        : "+f"(c[0]), "+f"(c[1]), "+f"(c[2]), "+f"(c[3])
        : "r"(a[0]), "r"(a[1]), "r"(a[2]), "r"(a[3]), "r"(b0), "r"(b1));
}
__device__ __forceinline__ uint32_t packh(float lo, float hi) {
    __half2 v = __floats2half2_rn(lo, hi);
    return *(uint32_t*)&v;
}

// ---------------------------------------------------------------------------
// conversions
// ---------------------------------------------------------------------------
__global__ __launch_bounds__(256) void cvt_inputs(
    const float* __restrict__ q, const float* __restrict__ k,
    const float* __restrict__ v,
    __half* __restrict__ q16, __half* __restrict__ k16,
    __half* __restrict__ vh, __half* __restrict__ vl)
{
    const int gid = blockIdx.x * 256 + threadIdx.x;
    if (gid < (3 << 20)) {
        const float* src = (gid < (1 << 20)) ? q : k;
        __half* dst = (gid < (1 << 20)) ? q16 : k16;
        const int idx = ((gid < (1 << 20)) ? gid : gid - (1 << 20)) * 4;
        float4 x = *(const float4*)(src + idx);
        *(__half2*)(dst + idx)     = __floats2half2_rn(x.x, x.y);
        *(__half2*)(dst + idx + 2) = __floats2half2_rn(x.z, x.w);
    } else {
        const int idx = (gid - (3 << 20)) * 4;
        float4 x = *(const float4*)(v + idx);
        __half h0 = __float2half_rn(x.x), h1 = __float2half_rn(x.y);
        __half h2 = __float2half_rn(x.z), h3 = __float2half_rn(x.w);
        *(__half2*)(vh + idx)     = __half2(h0, h1);
        *(__half2*)(vh + idx + 2) = __half2(h2, h3);
        *(__half2*)(vl + idx) = __half2(__float2half_rn(x.x - __half2float(h0)),
                                        __float2half_rn(x.y - __half2float(h1)));
        *(__half2*)(vl + idx + 2) = __half2(__float2half_rn(x.z - __half2float(h2)),
                                            __float2half_rn(x.w - __half2float(h3)));
    }
}

__global__ __launch_bounds__(256) void cvt_weights(
    const float* __restrict__ w0, const float* __restrict__ w1,
    const float* __restrict__ w2, const float* __restrict__ w3,
    __half* __restrict__ o0, __half* __restrict__ o1,
    __half* __restrict__ o2, __half* __restrict__ o3)
{
    const int gid = blockIdx.x * 256 + threadIdx.x;
    const int seg = gid >> 18;
    const int idx = (gid & 262143) * 4;
    const float* src = (seg == 0) ? w0 : (seg == 1) ? w1 : (seg == 2) ? w2 : w3;
    __half* dst = (seg == 0) ? o0 : (seg == 1) ? o1 : (seg == 2) ? o2 : o3;
    float4 x = *(const float4*)(src + idx);
    *(__half2*)(dst + idx)     = __floats2half2_rn(x.x, x.y);
    *(__half2*)(dst + idx + 2) = __floats2half2_rn(x.z, x.w);
}

__global__ __launch_bounds__(256) void log_mult(const float* __restrict__ m,
                                                float* __restrict__ lb) {
    int i = blockIdx.x * 256 + threadIdx.x;
    lb[i] = __logf(m[i]);
}

// ---------------------------------------------------------------------------
// Merged Q+K projection: single-term fp16 GEMM, fp16 out (Q scaled 0.125)
// Block 128x256, 8 warps 64x64, 4 stages, 2 k-tiles per barrier.
// grid.y in [0,96): y<32 -> Q tile, y>=32 -> K tile.
// ---------------------------------------------------------------------------
#define ROWB   80
#define A_MATB (128 * ROWB)               // 10240
#define B_MATB (256 * ROWB)               // 20480
#define S1_STG  (A_MATB + B_MATB)         // 30720
#define S1_SMEM (4 * S1_STG)              // 122880

__global__ __launch_bounds__(256) void proj_qk(
    const __half* __restrict__ Q16, const __half* __restrict__ K16,
    const __half* __restrict__ Wq, const __half* __restrict__ Wk,
    const float* __restrict__ Qb, const float* __restrict__ Kb,
    __half* __restrict__ Oq, __half* __restrict__ Ok)
{
    extern __shared__ __align__(1024) char sm[];
    const uint32_t sb = smem_u32(sm);
    const int tid = threadIdx.x;
    const int lane = tid & 31, wid = tid >> 5;
    const int warp_m = wid >> 2, warp_n = wid & 3;
    const int y = blockIdx.y;
    const bool isQ = (y < 32);
    const int bm = (isQ ? y : y - 32) * 128;
    const int bn = blockIdx.x * 256;
    const __half* A = isQ ? Q16 : K16;
    const __half* B = isQ ? Wq : Wk;
    const float* bias = isQ ? Qb : Kb;
    __half* Out = isQ ? Oq : Ok;
    const float sc = isQ ? 0.125f : 1.0f;
    const int Kd = EMBED, N = EMBED;

    const int lrw = tid >> 1;
    const int lck = (tid & 1) * 2;
    const __half* gA  = A + (size_t)(bm + lrw) * Kd + lck * 8;
    const __half* gB0 = B + (size_t)(bn + lrw) * Kd + lck * 8;
    const __half* gB1 = gB0 + (size_t)128 * Kd;
    const uint32_t dA  = lrw * ROWB + lck * 16;
    const uint32_t dB0 = A_MATB + lrw * ROWB + lck * 16;
    const uint32_t dB1 = dB0 + 128 * ROWB;

#define QISSUE(s, kt) do {                                                  \
        const uint32_t so = sb + (s) * S1_STG;                              \
        const size_t go = (size_t)(kt) * 32;                                \
        cp16(so + dA,       gA + go);                                       \
        cp16(so + dA + 16,  gA + go + 8);                                   \
        cp16(so + dB0,      gB0 + go);                                      \
        cp16(so + dB0 + 16, gB0 + go + 8);                                  \
        cp16(so + dB1,      gB1 + go);                                      \
        cp16(so + dB1 + 16, gB1 + go + 8);                                  \
        CP_COMMIT();                                                       \
    } while (0)

    QISSUE(0, 0);
    QISSUE(1, 1);

    float c[4][8][4];
#pragma unroll
    for (int i = 0; i < 4; i++)
#pragma unroll
        for (int j = 0; j < 8; j++)
#pragma unroll
            for (int q = 0; q < 4; q++) c[i][j][q] = 0.f;

    const uint32_t frow = lane & 15;
    const uint32_t fkb  = ((lane >> 4) & 1) * 16;
    const uint32_t aBase = (warp_m * 64 + frow) * ROWB + fkb;
    const uint32_t bBase = A_MATB + (warp_n * 64 + frow) * ROWB + fkb;

    const int NKT = Kd / 32;   // 32
#pragma unroll 1
    for (int kt = 0; kt < NKT; kt += 2) {
        CP_WAIT(0);
        __syncthreads();
        if (kt + 2 < NKT) { QISSUE((kt + 2) & 3, kt + 2); QISSUE((kt + 3) & 3, kt + 3); }

#pragma unroll
        for (int s = 0; s < 2; s++) {
            const uint32_t st = sb + ((kt + s) & 3) * S1_STG;
#pragma unroll
            for (int ks = 0; ks < 2; ks++) {
                const uint32_t ko = ks * 32;
                uint32_t ah[4][4];
#pragma unroll
                for (int mi = 0; mi < 4; mi++)
                    ldsm4(ah[mi], st + aBase + mi * 16 * ROWB + ko);
#pragma unroll
                for (int nb = 0; nb < 4; nb++) {
                    uint32_t bh[4];
                    ldsm4(bh, st + bBase + nb * 16 * ROWB + ko);
#pragma unroll
                    for (int mi = 0; mi < 4; mi++) {
                        mma_h(c[mi][nb * 2],     ah[mi], bh[0], bh[2]);
                        mma_h(c[mi][nb * 2 + 1], ah[mi], bh[1], bh[3]);
                    }
                }
            }
        }
    }

    const int erow = lane >> 2, ecol = (lane & 3) * 2;
#pragma unroll
    for (int mi = 0; mi < 4; mi++) {
        const int r0 = bm + warp_m * 64 + mi * 16 + erow;
#pragma unroll
        for (int n8 = 0; n8 < 8; n8++) {
            const int cc = bn + warp_n * 64 + n8 * 8 + ecol;
            const float b0 = bias[cc], b1 = bias[cc + 1];
            size_t i0 = (size_t)r0 * N + cc, i1 = (size_t)(r0 + 8) * N + cc;
            *(uint32_t*)(Out + i0) = packh((c[mi][n8][0] + b0) * sc,
                                           (c[mi][n8][1] + b1) * sc);
            *(uint32_t*)(Out + i1) = packh((c[mi][n8][2] + b0) * sc,
                                           (c[mi][n8][3] + b1) * sc);
        }
    }
#undef QISSUE
}

// ---------------------------------------------------------------------------
// 2-term fp16 GEMM: C = (Ah+Al) B^T + bias. 4 stages, 2 k-tiles per barrier.
// MODE 0: fp32 out; MODE 3: transposed fp16 V^T [b][h][d][key]
// ---------------------------------------------------------------------------
#define S2_STG  (2 * A_MATB + B_MATB)     // 40960
#define S2_SMEM (4 * S2_STG)              // 163840

template<int MODE>
__global__ __launch_bounds__(256) void gemm2(
    const __half* __restrict__ Ah, const __half* __restrict__ Al,
    const __half* __restrict__ Bh, const float* __restrict__ bias,
    float* __restrict__ C, __half* __restrict__ VT,
    int M, int N, int K)
{
    extern __shared__ __align__(1024) char sm[];
    const uint32_t sb = smem_u32(sm);
    const int tid = threadIdx.x;
    const int lane = tid & 31, wid = tid >> 5;
    const int warp_m = wid >> 2, warp_n = wid & 3;
    const int bm = blockIdx.y * 128, bn = blockIdx.x * 256;

    const int lrw = tid >> 1;
    const int lck = (tid & 1) * 2;
    const __half* gAh = Ah + (size_t)(bm + lrw) * K + lck * 8;
    const __half* gAl = Al + (size_t)(bm + lrw) * K + lck * 8;
    const __half* gB0 = Bh + (size_t)(bn + lrw) * K + lck * 8;
    const __half* gB1 = gB0 + (size_t)128 * K;
    const uint32_t dA  = lrw * ROWB + lck * 16;
    const uint32_t dB0 = 2 * A_MATB + lrw * ROWB + lck * 16;
    const uint32_t dB1 = dB0 + 128 * ROWB;

#define GISSUE(s, kt) do {                                                  \
        const uint32_t so = sb + (s) * S2_STG;                              \
        const size_t go = (size_t)(kt) * 32;                                \
        cp16(so + dA,               gAh + go);                              \
        cp16(so + dA + 16,          gAh + go + 8);                          \
        cp16(so + dA + A_MATB,      gAl + go);                              \
        cp16(so + dA + A_MATB + 16, gAl + go + 8);                          \
        cp16(so + dB0,              gB0 + go);                              \
        cp16(so + dB0 + 16,         gB0 + go + 8);                          \
        cp16(so + dB1,              gB1 + go);                              \
        cp16(so + dB1 + 16,         gB1 + go + 8);                          \
        CP_COMMIT();                                                       \
    } while (0)

    GISSUE(0, 0);
    GISSUE(1, 1);

    float c[4][8][4];
#pragma unroll
    for (int i = 0; i < 4; i++)
#pragma unroll
        for (int j = 0; j < 8; j++)
#pragma unroll
            for (int q = 0; q < 4; q++) c[i][j][q] = 0.f;

    const uint32_t frow = lane & 15;
    const uint32_t fkb  = ((lane >> 4) & 1) * 16;
    const uint32_t aBase = (warp_m * 64 + frow) * ROWB + fkb;
    const uint32_t bBase = 2 * A_MATB + (warp_n * 64 + frow) * ROWB + fkb;

    const int NKT = K / 32;
#pragma unroll 1
    for (int kt = 0; kt < NKT; kt += 2) {
        CP_WAIT(0);
        __syncthreads();
        if (kt + 2 < NKT) { GISSUE((kt + 2) & 3, kt + 2); GISSUE((kt + 3) & 3, kt + 3); }

#pragma unroll
        for (int s = 0; s < 2; s++) {
            const uint32_t st = sb + ((kt + s) & 3) * S2_STG;
#pragma unroll
            for (int ks = 0; ks < 2; ks++) {
                const uint32_t ko = ks * 32;
                uint32_t ah[4][4], al_[4][4];
#pragma unroll
                for (int mi = 0; mi < 4; mi++) {
                    ldsm4(ah[mi],  st + aBase + mi * 16 * ROWB + ko);
                    ldsm4(al_[mi], st + A_MATB + aBase + mi * 16 * ROWB + ko);
                }
#pragma unroll
                for (int nb = 0; nb < 4; nb++) {
                    uint32_t bh[4];
                    ldsm4(bh, st + bBase + nb * 16 * ROWB + ko);
#pragma unroll
                    for (int mi = 0; mi < 4; mi++) {
                        mma_h(c[mi][nb * 2],     ah[mi],  bh[0], bh[2]);
                        mma_h(c[mi][nb * 2],     al_[mi], bh[0], bh[2]);
                        mma_h(c[mi][nb * 2 + 1], ah[mi],  bh[1], bh[3]);
                        mma_h(c[mi][nb * 2 + 1], al_[mi], bh[1], bh[3]);
                    }
                }
            }
        }
    }

    const int erow = lane >> 2, ecol = (lane & 3) * 2;
#pragma unroll
    for (int mi = 0; mi < 4; mi++) {
        const int r0 = bm + warp_m * 64 + mi * 16 + erow;
#pragma unroll
        for (int n8 = 0; n8 < 8; n8++) {
            const int cc = bn + warp_n * 64 + n8 * 8 + ecol;
            const float b0 = bias[cc], b1 = bias[cc + 1];
            if (MODE == 0) {
                float2 v0 = {c[mi][n8][0] + b0, c[mi][n8][1] + b1};
                float2 v1 = {c[mi][n8][2] + b0, c[mi][n8][3] + b1};
                *(float2*)(C + (size_t)r0 * N + cc)       = v0;
                *(float2*)(C + (size_t)(r0 + 8) * N + cc) = v1;
            } else {
#pragma unroll
                for (int rr = 0; rr < 2; rr++) {
                    const int r = r0 + rr * 8;
                    const int bb = r >> 11, key = r & (NKV - 1);
                    const float v0 = c[mi][n8][rr * 2]     + b0;
                    const float v1 = c[mi][n8][rr * 2 + 1] + b1;
                    const size_t o0 = ((size_t)((bb * NH + (cc >> 6)) * HD + (cc & 63))) * NKV + key;
                    const size_t o1 = ((size_t)((bb * NH + ((cc + 1) >> 6)) * HD + ((cc + 1) & 63))) * NKV + key;
                    VT[o0] = __float2half_rn(v0);
                    VT[o1] = __float2half_rn(v1);
                }
            }
        }
    }
#undef GISSUE
}

// ---------------------------------------------------------------------------
// fp16 HMMA flash attention (single-term): S = Q K^T + log m; O = P V
// (unchanged from round 14)
// ---------------------------------------------------------------------------
#define QROW 144
#define SQ_SZ  (128 * QROW)               // 18432
#define SV     (64 * QROW)                // 9216
#define SLB    (2 * 64 * QROW)            // 18432
#define STG_SZ (2 * 64 * QROW + 256)      // 18688
#define ASMEM  (SQ_SZ + 3 * STG_SZ)       // 74496

__global__ __launch_bounds__(256) void attn_hmma(
    const __half* __restrict__ Qf, const __half* __restrict__ Kf,
    const __half* __restrict__ VT, const float* __restrict__ lbG,
    __half* __restrict__ Oh, __half* __restrict__ Ol)
{
    extern __shared__ __align__(1024) char sm[];
    const uint32_t sb = smem_u32(sm);
    const int qt = blockIdx.x, h = blockIdx.y, b = blockIdx.z;
    const int tid = threadIdx.x;
    const int lane = tid & 31, wid = tid >> 5;

    {
        const int row = tid >> 1;
        const int co = (tid & 1) * 32;
        const __half* gq = Qf + ((size_t)(b * NQV + qt * 128 + row)) * EMBED + h * HD + co;
        const uint32_t dq = sb + row * QROW + co * 2;
#pragma unroll
        for (int i = 0; i < 4; i++) cp16(dq + i * 16, gq + i * 8);
    }

    const int srow = tid >> 2, scq = tid & 3;
    const __half* gK = Kf + ((size_t)(b * NKV + srow)) * EMBED + h * HD + scq * 16;
    const __half* gV = VT + ((size_t)((b * NH + h) * HD + srow)) * NKV + scq * 16;
    const uint32_t sdst = srow * QROW + scq * 32;
    const float* gLB = lbG + (size_t)b * NKV;

#define AISSUE(s, kt) do {                                                  \
        const uint32_t so = sb + SQ_SZ + (s) * STG_SZ;                      \
        const size_t koK = (size_t)(kt) * 64 * EMBED;                       \
        const size_t koV = (size_t)(kt) * 64;                               \
        cp16(so + sdst,           gK + koK);                                \
        cp16(so + sdst + 16,      gK + koK + 8);                            \
        cp16(so + SV + sdst,      gV + koV);                                \
        cp16(so + SV + sdst + 16, gV + koV + 8);                            \
        if (tid < 16) cp16(so + SLB + tid * 16, gLB + (kt) * 64 + tid * 4); \
        CP_COMMIT();                                                       \
    } while (0)

    AISSUE(0, 0);
    AISSUE(1, 1);

    const uint32_t frow = lane & 15;
    const uint32_t fkb  = ((lane >> 4) & 1) * 16;
    const uint32_t qBase = (wid * 16 + frow) * QROW + fkb;
    uint32_t qhf[4][4];

    float o[8][4];
#pragma unroll
    for (int j = 0; j < 8; j++)
#pragma unroll
        for (int q = 0; q < 4; q++) o[j][q] = 0.f;
    float m0 = -1e30f, m1 = -1e30f, l0 = 0.f, l1 = 0.f;

    const int NT = NKV / 64;
#pragma unroll 1
    for (int kt = 0; kt < NT; kt++) {
        if (kt + 1 < NT) { CP_WAIT(1); } else { CP_WAIT(0); }
        __syncthreads();
        if (kt == 0) {
#pragma unroll
            for (int ks = 0; ks < 4; ks++) ldsm4(qhf[ks], sb + qBase + ks * 32);
        }
        if (kt + 2 < NT) AISSUE((kt + 2) % 3, kt + 2);
        const uint32_t st = sb + SQ_SZ + (kt % 3) * STG_SZ;

        float c[8][4];
#pragma unroll
        for (int j = 0; j < 8; j++)
#pragma unroll
            for (int q = 0; q < 4; q++) c[j][q] = 0.f;

#pragma unroll
        for (int ks = 0; ks < 4; ks++) {
#pragma unroll
            for (int nb = 0; nb < 4; nb++) {
                uint32_t kf[4];
                ldsm4(kf, st + (nb * 16 + frow) * QROW + fkb + ks * 32);
                mma_h(c[nb * 2],     qhf[ks], kf[0], kf[2]);
                mma_h(c[nb * 2 + 1], qhf[ks], kf[1], kf[3]);
            }
        }

        const float* lbs = (const float*)(sm + SQ_SZ + (kt % 3) * STG_SZ + SLB);
#pragma unroll
        for (int j = 0; j < 8; j++) {
            float2 lb2 = *(const float2*)(lbs + j * 8 + (lane & 3) * 2);
            c[j][0] += lb2.x; c[j][1] += lb2.y;
            c[j][2] += lb2.x; c[j][3] += lb2.y;
        }

        float rm0 = -1e30f, rm1 = -1e30f;
#pragma unroll
        for (int j = 0; j < 8; j++) {
            rm0 = fmaxf(rm0, fmaxf(c[j][0], c[j][1]));
            rm1 = fmaxf(rm1, fmaxf(c[j][2], c[j][3]));
        }
#pragma unroll
        for (int off = 1; off < 4; off <<= 1) {
            rm0 = fmaxf(rm0, __shfl_xor_sync(0xffffffffu, rm0, off));
            rm1 = fmaxf(rm1, __shfl_xor_sync(0xffffffffu, rm1, off));
        }
        const float mn0 = fmaxf(m0, rm0), mn1 = fmaxf(m1, rm1);
        const float al0 = __expf(m0 - mn0), al1 = __expf(m1 - mn1);
        float rs0 = 0.f, rs1 = 0.f;
#pragma unroll
        for (int j = 0; j < 8; j++) {
            c[j][0] = __expf(c[j][0] - mn0); rs0 += c[j][0];
            c[j][1] = __expf(c[j][1] - mn0); rs0 += c[j][1];
            c[j][2] = __expf(c[j][2] - mn1); rs1 += c[j][2];
            c[j][3] = __expf(c[j][3] - mn1); rs1 += c[j][3];
        }
#pragma unroll
        for (int off = 1; off < 4; off <<= 1) {
            rs0 += __shfl_xor_sync(0xffffffffu, rs0, off);
            rs1 += __shfl_xor_sync(0xffffffffu, rs1, off);
        }
        l0 = l0 * al0 + rs0;  m0 = mn0;
        l1 = l1 * al1 + rs1;  m1 = mn1;
#pragma unroll
        for (int j = 0; j < 8; j++) {
            o[j][0] *= al0; o[j][1] *= al0;
            o[j][2] *= al1; o[j][3] *= al1;
        }

#pragma unroll
        for (int kk = 0; kk < 4; kk++) {
            const int j0 = 2 * kk, j1 = 2 * kk + 1;
            uint32_t ah[4];
            ah[0] = packh(c[j0][0], c[j0][1]);
            ah[1] = packh(c[j0][2], c[j0][3]);
            ah[2] = packh(c[j1][0], c[j1][1]);
            ah[3] = packh(c[j1][2], c[j1][3]);
#pragma unroll
            for (int nb = 0; nb < 4; nb++) {
                uint32_t vh[4];
                ldsm4(vh, st + SV + (nb * 16 + frow) * QROW + fkb + kk * 32);
                mma_h(o[nb * 2],     ah, vh[0], vh[2]);
                mma_h(o[nb * 2 + 1], ah, vh[1], vh[3]);
            }
        }
    }

    const float inv0 = 1.f / l0, inv1 = 1.f / l1;
    const int r0 = qt * 128 + wid * 16 + (lane >> 2);
    const int cc0 = h * HD + (lane & 3) * 2;
#pragma unroll
    for (int j = 0; j < 8; j++) {
        const int col = cc0 + j * 8;
        {
            float v0 = o[j][0] * inv0, v1 = o[j][1] * inv0;
            float h0 = __half2float(__float2half_rn(v0));
            float h1 = __half2float(__float2half_rn(v1));
            size_t idx = ((size_t)(b * NQV + r0)) * EMBED + col;
            *(uint32_t*)(Oh + idx) = packh(h0, h1);
            *(uint32_t*)(Ol + idx) = packh(v0 - h0, v1 - h1);
        }
        {
            float v0 = o[j][2] * inv1, v1 = o[j][3] * inv1;
            float h0 = __half2float(__float2half_rn(v0));
            float h1 = __half2float(__float2half_rn(v1));
            size_t idx = ((size_t)(b * NQV + r0 + 8)) * EMBED + col;
            *(uint32_t*)(Oh + idx) = packh(h0, h1);
            *(uint32_t*)(Ol + idx) = packh(v0 - h0, v1 - h1);
        }
    }
#undef AISSUE
}

// ---------------------------------------------------------------------------
extern "C" void kernel_launch(void* const* d_in, const int* in_sizes, int n_in,
                              void* d_out, int out_size)
{
    const float* query = (const float*)d_in[0];
    const float* key   = (const float*)d_in[1];
    const float* value = (const float*)d_in[2];
    const float* mult  = (const float*)d_in[3];
    const float* wq_w  = (const float*)d_in[4];
    const float* wq_b  = (const float*)d_in[5];
    const float* wk_w  = (const float*)d_in[6];
    const float* wk_b  = (const float*)d_in[7];
    const float* wv_w  = (const float*)d_in[8];
    const float* wv_b  = (const float*)d_in[9];
    const float* wo_w  = (const float*)d_in[10];
    const float* wo_b  = (const float*)d_in[11];
    float* out = (float*)d_out;

    float* glb;  cudaGetSymbolAddress((void**)&glb, g_lb);
    __half *q16,*k16,*v16h,*v16l;
    __half *wq16,*wk16,*wv16,*wo16;
    __half *qs16,*ks16,*vt16,*ao16h,*ao16l;
    cudaGetSymbolAddress((void**)&q16, g_q16);
    cudaGetSymbolAddress((void**)&k16, g_k16);
    cudaGetSymbolAddress((void**)&v16h, g_v16h); cudaGetSymbolAddress((void**)&v16l, g_v16l);
    cudaGetSymbolAddress((void**)&wq16, g_wq16); cudaGetSymbolAddress((void**)&wk16, g_wk16);
    cudaGetSymbolAddress((void**)&wv16, g_wv16); cudaGetSymbolAddress((void**)&wo16, g_wo16);
    cudaGetSymbolAddress((void**)&qs16, g_qs16);
    cudaGetSymbolAddress((void**)&ks16, g_ks16);
    cudaGetSymbolAddress((void**)&vt16, g_vt16);
    cudaGetSymbolAddress((void**)&ao16h, g_ao16h); cudaGetSymbolAddress((void**)&ao16l, g_ao16l);

    cudaFuncSetAttribute(proj_qk, cudaFuncAttributeMaxDynamicSharedMemorySize, S1_SMEM);
    cudaFuncSetAttribute((void*)gemm2<0>, cudaFuncAttributeMaxDynamicSharedMemorySize, S2_SMEM);
    cudaFuncSetAttribute((void*)gemm2<3>, cudaFuncAttributeMaxDynamicSharedMemorySize, S2_SMEM);
    cudaFuncSetAttribute(attn_hmma, cudaFuncAttributeMaxDynamicSharedMemorySize, ASMEM);

    const int MQ = BATCH * NQV;   // 4096
    const int MK = BATCH * NKV;   // 8192

    // 0: inputs -> fp16 (q,k single; v hi/lo)
    cvt_inputs<<<20480, 256>>>(query, key, value, q16, k16, v16h, v16l);
    // 1: weights -> fp16
    cvt_weights<<<4096, 256>>>(wq_w, wk_w, wv_w, wo_w, wq16, wk16, wv16, wo16);
    // 2: log multiplicities
    log_mult<<<MK / 256, 256>>>(mult, glb);
    // 3: merged Q+K projection (Q scaled 0.125)
    proj_qk<<<dim3(EMBED / 256, (MQ + MK) / 128), 256, S1_SMEM>>>(
        q16, k16, wq16, wk16, wq_b, wk_b, qs16, ks16);
    // 4: V proj (2-term) -> transposed fp16 V^T
    gemm2<3><<<dim3(EMBED / 256, MK / 128), 256, S2_SMEM>>>(
        v16h, v16l, wv16, wv_b, nullptr, vt16, MK, EMBED, EMBED);
    // 5 (ncu): attention
    attn_hmma<<<dim3(NQV / 128, NH, BATCH), 256, ASMEM>>>(
        qs16, ks16, vt16, glb, ao16h, ao16l);
    // 6: O proj (2-term) -> fp32 out
    gemm2<0><<<dim3(EMBED / 256, MQ / 128), 256, S2_SMEM>>>(
        ao16h, ao16l, wo16, wo_b, out, nullptr, MQ, EMBED, EMBED);
}

// round 16
// speedup vs baseline: 1.3044x; 1.2966x over previous
#include <cuda_runtime.h>
#include <cuda_fp16.h>
#include <math.h>
#include <stdint.h>

#define EMBED 1024
#define NQV   1024
#define NKV   2048
#define BATCH 4
#define NH    16
#define HD    64

// ---------------------------------------------------------------------------
// Scratch (__device__ globals — allocation-free rule)
// ---------------------------------------------------------------------------
__device__ float g_lb[BATCH * NKV];

__device__ __half g_q16[BATCH * NQV * EMBED];      // single fp16 input
__device__ __half g_k16[BATCH * NKV * EMBED];      // single fp16 input
__device__ __half g_v16h[BATCH * NKV * EMBED], g_v16l[BATCH * NKV * EMBED];
__device__ __half g_wq16[EMBED * EMBED], g_wk16[EMBED * EMBED];
__device__ __half g_wv16[EMBED * EMBED], g_wo16[EMBED * EMBED];
__device__ __half g_qs16h[BATCH * NQV * EMBED], g_qs16l[BATCH * NQV * EMBED];
__device__ __half g_ks16[BATCH * NKV * EMBED];
__device__ __half g_vt16[BATCH * NH * HD * NKV];
__device__ __half g_ao16h[BATCH * NQV * EMBED], g_ao16l[BATCH * NQV * EMBED];

// ---------------------------------------------------------------------------
// PTX helpers (sm_80-compatible ISA: compute_103 has no 'a' features)
// ---------------------------------------------------------------------------
__device__ __forceinline__ uint32_t smem_u32(const void* p) {
    uint32_t a;
    asm("{ .reg .u64 t; cvta.to.shared.u64 t, %1; cvt.u32.u64 %0, t; }"
        : "=r"(a) : "l"(p));
    return a;
}
__device__ __forceinline__ void cp16(uint32_t dst, const void* src) {
    asm volatile("cp.async.cg.shared.global [%0], [%1], 16;"
                 :: "r"(dst), "l"(src) : "memory");
}
#define CP_COMMIT() asm volatile("cp.async.commit_group;" ::: "memory")
#define CP_WAIT(n)  asm volatile("cp.async.wait_group %0;" :: "n"(n) : "memory")

__device__ __forceinline__ void ldsm4(uint32_t* r, uint32_t addr) {
    asm volatile("ldmatrix.sync.aligned.m8n8.x4.shared.b16 {%0,%1,%2,%3}, [%4];"
                 : "=r"(r[0]), "=r"(r[1]), "=r"(r[2]), "=r"(r[3]) : "r"(addr));
}
__device__ __forceinline__ void mma_h(float* c, const uint32_t* a,
                                      uint32_t b0, uint32_t b1) {
    asm volatile(
        "mma.sync.aligned.m16n8k16.row.col.f32.f16.f16.f32 "
        "{%0,%1,%2,%3}, {%4,%5,%6,%7}, {%8,%9}, {%0,%1,%2,%3};"
        : "+f"(c[0]), "+f"(c[1]), "+f"(c[2]), "+f"(c[3])
        : "r"(a[0]), "r"(a[1]), "r"(a[2]), "r"(a[3]), "r"(b0), "r"(b1));
}
__device__ __forceinline__ uint32_t packh(float lo, float hi) {
    __half2 v = __floats2half2_rn(lo, hi);
    return *(uint32_t*)&v;
}

// ---------------------------------------------------------------------------
// conversions: q single | k single | v hi/lo
// ---------------------------------------------------------------------------
__global__ __launch_bounds__(256) void cvt_inputs(
    const float* __restrict__ q, const float* __restrict__ k,
    const float* __restrict__ v,
    __half* __restrict__ q16, __half* __restrict__ k16,
    __half* __restrict__ vh, __half* __restrict__ vl)
{
    const int gid = blockIdx.x * 256 + threadIdx.x;
    if (gid < (3 << 20)) {
        const float* src = (gid < (1 << 20)) ? q : k;
        __half* dst = (gid < (1 << 20)) ? q16 : k16;
        const int idx = ((gid < (1 << 20)) ? gid : gid - (1 << 20)) * 4;
        float4 x = *(const float4*)(src + idx);
        *(__half2*)(dst + idx)     = __floats2half2_rn(x.x, x.y);
        *(__half2*)(dst + idx + 2) = __floats2half2_rn(x.z, x.w);
    } else {
        const int idx = (gid - (3 << 20)) * 4;
        float4 x = *(const float4*)(v + idx);
        __half h0 = __float2half_rn(x.x), h1 = __float2half_rn(x.y);
        __half h2 = __float2half_rn(x.z), h3 = __float2half_rn(x.w);
        *(__half2*)(vh + idx)     = __half2(h0, h1);
        *(__half2*)(vh + idx + 2) = __half2(h2, h3);
        *(__half2*)(vl + idx) = __half2(__float2half_rn(x.x - __half2float(h0)),
                                        __float2half_rn(x.y - __half2float(h1)));
        *(__half2*)(vl + idx + 2) = __half2(__float2half_rn(x.z - __half2float(h2)),
                                            __float2half_rn(x.w - __half2float(h3)));
    }
}

__global__ __launch_bounds__(256) void cvt_weights(
    const float* __restrict__ w0, const float* __restrict__ w1,
    const float* __restrict__ w2, const float* __restrict__ w3,
    __half* __restrict__ o0, __half* __restrict__ o1,
    __half* __restrict__ o2, __half* __restrict__ o3)
{
    const int gid = blockIdx.x * 256 + threadIdx.x;
    const int seg = gid >> 18;
    const int idx = (gid & 262143) * 4;
    const float* src = (seg == 0) ? w0 : (seg == 1) ? w1 : (seg == 2) ? w2 : w3;
    __half* dst = (seg == 0) ? o0 : (seg == 1) ? o1 : (seg == 2) ? o2 : o3;
    float4 x = *(const float4*)(src + idx);
    *(__half2*)(dst + idx)     = __floats2half2_rn(x.x, x.y);
    *(__half2*)(dst + idx + 2) = __floats2half2_rn(x.z, x.w);
}

__global__ __launch_bounds__(256) void log_mult(const float* __restrict__ m,
                                                float* __restrict__ lb) {
    int i = blockIdx.x * 256 + threadIdx.x;
    lb[i] = __logf(m[i]);
}

// ---------------------------------------------------------------------------
// fp16 HMMA GEMM (round-11 shape): C = (Ah [+ Al]) B^T + bias
// Block 128x256, 8 warps 64x64, k-tile 32, 3 stages, 1 k-tile/iter.
// TWOTERM: 1 -> A = Ah + Al; 0 -> A = Ah only.
// MODE 0: fp32 out; MODE 3: transposed fp16 V^T [b][h][d][key];
// MODE 4: fp16 hi/lo out scaled 0.125; MODE 5: fp16 single out
// ---------------------------------------------------------------------------
#define ROWB   80
#define A_MATB (128 * ROWB)
#define B_MATB (256 * ROWB)
#define F2_STG  (2 * A_MATB + B_MATB)      // 40960
#define F2_SMEM (3 * F2_STG)               // 122880

template<int MODE, int TWOTERM>
__global__ __launch_bounds__(256) void gemm_f2(
    const __half* __restrict__ Ah, const __half* __restrict__ Al,
    const __half* __restrict__ Bh, const float* __restrict__ bias,
    float* __restrict__ C, __half* __restrict__ VT,
    __half* __restrict__ Oh, __half* __restrict__ Ol,
    int M, int N, int K)
{
    extern __shared__ __align__(1024) char sm[];
    const uint32_t sb = smem_u32(sm);
    const int tid = threadIdx.x;
    const int lane = tid & 31, wid = tid >> 5;
    const int warp_m = wid >> 2, warp_n = wid & 3;
    const int bm = blockIdx.y * 128, bn = blockIdx.x * 256;

    const int lrw = tid >> 1;
    const int lck = (tid & 1) * 2;
    const __half* gAh = Ah + (size_t)(bm + lrw) * K + lck * 8;
    const __half* gAl = TWOTERM ? (Al + (size_t)(bm + lrw) * K + lck * 8) : nullptr;
    const __half* gBh0 = Bh + (size_t)(bn + lrw) * K + lck * 8;
    const __half* gBh1 = gBh0 + (size_t)128 * K;
    const uint32_t dA  = lrw * ROWB + lck * 16;
    const uint32_t dB0 = 2 * A_MATB + lrw * ROWB + lck * 16;
    const uint32_t dB1 = dB0 + 128 * ROWB;

    const int NKT = K / 32;

#define ISSUE(s, kt) do {                                                   \
        const uint32_t so = sb + (s) * F2_STG;                              \
        const size_t go = (size_t)(kt) * 32;                                \
        cp16(so + dA,               gAh + go);                              \
        cp16(so + dA + 16,          gAh + go + 8);                          \
        if (TWOTERM) {                                                      \
            cp16(so + dA + A_MATB,      gAl + go);                          \
            cp16(so + dA + A_MATB + 16, gAl + go + 8);                      \
        }                                                                   \
        cp16(so + dB0,              gBh0 + go);                             \
        cp16(so + dB0 + 16,         gBh0 + go + 8);                         \
        cp16(so + dB1,              gBh1 + go);                             \
        cp16(so + dB1 + 16,         gBh1 + go + 8);                         \
        CP_COMMIT();                                                       \
    } while (0)

    ISSUE(0, 0);
    ISSUE(1, 1);

    float c[4][8][4];
#pragma unroll
    for (int i = 0; i < 4; i++)
#pragma unroll
        for (int j = 0; j < 8; j++)
#pragma unroll
            for (int q = 0; q < 4; q++) c[i][j][q] = 0.f;

    const uint32_t frow = lane & 15;
    const uint32_t fkb  = ((lane >> 4) & 1) * 16;
    const uint32_t aBase = (warp_m * 64 + frow) * ROWB + fkb;
    const uint32_t bBase = 2 * A_MATB + (warp_n * 64 + frow) * ROWB + fkb;

#pragma unroll 1
    for (int kt = 0; kt < NKT; kt++) {
        if (kt + 1 < NKT) { CP_WAIT(1); } else { CP_WAIT(0); }
        __syncthreads();
        if (kt + 2 < NKT) ISSUE((kt + 2) % 3, kt + 2);
        const uint32_t st = sb + (kt % 3) * F2_STG;

#pragma unroll
        for (int ks = 0; ks < 2; ks++) {
            const uint32_t ko = ks * 32;
            uint32_t ah[4][4], al_[4][4];
#pragma unroll
            for (int mi = 0; mi < 4; mi++) {
                ldsm4(ah[mi], st + aBase + mi * 16 * ROWB + ko);
                if (TWOTERM)
                    ldsm4(al_[mi], st + A_MATB + aBase + mi * 16 * ROWB + ko);
            }
#pragma unroll
            for (int nb = 0; nb < 4; nb++) {
                uint32_t bh[4];
                ldsm4(bh, st + bBase + nb * 16 * ROWB + ko);
#pragma unroll
                for (int mi = 0; mi < 4; mi++) {
                    mma_h(c[mi][nb * 2],     ah[mi], bh[0], bh[2]);
                    mma_h(c[mi][nb * 2 + 1], ah[mi], bh[1], bh[3]);
                    if (TWOTERM) {
                        mma_h(c[mi][nb * 2],     al_[mi], bh[0], bh[2]);
                        mma_h(c[mi][nb * 2 + 1], al_[mi], bh[1], bh[3]);
                    }
                }
            }
        }
    }

    const int erow = lane >> 2, ecol = (lane & 3) * 2;
#pragma unroll
    for (int mi = 0; mi < 4; mi++) {
        const int r0 = bm + warp_m * 64 + mi * 16 + erow;
#pragma unroll
        for (int n8 = 0; n8 < 8; n8++) {
            const int cc = bn + warp_n * 64 + n8 * 8 + ecol;
            const float b0 = bias[cc], b1 = bias[cc + 1];
            if (MODE == 0) {
                float2 v0 = {c[mi][n8][0] + b0, c[mi][n8][1] + b1};
                float2 v1 = {c[mi][n8][2] + b0, c[mi][n8][3] + b1};
                *(float2*)(C + (size_t)r0 * N + cc)       = v0;
                *(float2*)(C + (size_t)(r0 + 8) * N + cc) = v1;
            } else if (MODE == 3) {
#pragma unroll
                for (int rr = 0; rr < 2; rr++) {
                    const int r = r0 + rr * 8;
                    const int bb = r >> 11, key = r & (NKV - 1);
                    const float v0 = c[mi][n8][rr * 2]     + b0;
                    const float v1 = c[mi][n8][rr * 2 + 1] + b1;
                    const size_t o0 = ((size_t)((bb * NH + (cc >> 6)) * HD + (cc & 63))) * NKV + key;
                    const size_t o1 = ((size_t)((bb * NH + ((cc + 1) >> 6)) * HD + ((cc + 1) & 63))) * NKV + key;
                    VT[o0] = __float2half_rn(v0);
                    VT[o1] = __float2half_rn(v1);
                }
            } else if (MODE == 4) {
                float x0 = (c[mi][n8][0] + b0) * 0.125f, x1 = (c[mi][n8][1] + b1) * 0.125f;
                float x2 = (c[mi][n8][2] + b0) * 0.125f, x3 = (c[mi][n8][3] + b1) * 0.125f;
                float h0 = __half2float(__float2half_rn(x0));
                float h1 = __half2float(__float2half_rn(x1));
                float h2 = __half2float(__float2half_rn(x2));
                float h3 = __half2float(__float2half_rn(x3));
                size_t i0 = (size_t)r0 * N + cc, i1 = (size_t)(r0 + 8) * N + cc;
                *(uint32_t*)(Oh + i0) = packh(h0, h1);
                *(uint32_t*)(Oh + i1) = packh(h2, h3);
                *(uint32_t*)(Ol + i0) = packh(x0 - h0, x1 - h1);
                *(uint32_t*)(Ol + i1) = packh(x2 - h2, x3 - h3);
            } else {  // MODE 5: fp16 single
                size_t i0 = (size_t)r0 * N + cc, i1 = (size_t)(r0 + 8) * N + cc;
                *(uint32_t*)(Oh + i0) = packh(c[mi][n8][0] + b0, c[mi][n8][1] + b1);
                *(uint32_t*)(Oh + i1) = packh(c[mi][n8][2] + b0, c[mi][n8][3] + b1);
            }
        }
    }
#undef ISSUE
}

// ---------------------------------------------------------------------------
// fp16 HMMA flash attention — EXACT round-11 version (known 705 µs config):
// S = (Qh+Ql)K^T + log m; O = (Ph+Pl)V; 3 stages.
// ---------------------------------------------------------------------------
#define QROW 144
#define SQ_L   (128 * QROW)               // 18432
#define SQ_SZ  (2 * 128 * QROW)           // 36864
#define SV     (64 * QROW)                // 9216
#define SLB    (2 * 64 * QROW)            // 18432
#define STG_SZ (2 * 64 * QROW + 256)      // 18688
#define ASMEM  (SQ_SZ + 3 * STG_SZ)       // 92928

__global__ __launch_bounds__(256) void attn_hmma(
    const __half* __restrict__ Qh, const __half* __restrict__ Ql,
    const __half* __restrict__ Kf, const __half* __restrict__ VT,
    const float* __restrict__ lbG,
    __half* __restrict__ Oh, __half* __restrict__ Ol)
{
    extern __shared__ __align__(1024) char sm[];
    const uint32_t sb = smem_u32(sm);
    const int qt = blockIdx.x, h = blockIdx.y, b = blockIdx.z;
    const int tid = threadIdx.x;
    const int lane = tid & 31, wid = tid >> 5;

    // Q tile via cp.async (pre-scaled hi/lo)
    {
        const int row = tid >> 1;
        const int co = (tid & 1) * 32;
        const __half* gqh = Qh + ((size_t)(b * NQV + qt * 128 + row)) * EMBED + h * HD + co;
        const __half* gql = Ql + ((size_t)(b * NQV + qt * 128 + row)) * EMBED + h * HD + co;
        const uint32_t dh = sb + row * QROW + co * 2;
        const uint32_t dl = sb + SQ_L + row * QROW + co * 2;
#pragma unroll
        for (int i = 0; i < 4; i++) {
            cp16(dh + i * 16, gqh + i * 8);
            cp16(dl + i * 16, gql + i * 8);
        }
    }

    const int srow = tid >> 2, scq = tid & 3;
    const __half* gK = Kf + ((size_t)(b * NKV + srow)) * EMBED + h * HD + scq * 16;
    const __half* gV = VT + ((size_t)((b * NH + h) * HD + srow)) * NKV + scq * 16;
    const uint32_t sdst = srow * QROW + scq * 32;
    const float* gLB = lbG + (size_t)b * NKV;

#define AISSUE(s, kt) do {                                                  \
        const uint32_t so = sb + SQ_SZ + (s) * STG_SZ;                      \
        const size_t koK = (size_t)(kt) * 64 * EMBED;                       \
        const size_t koV = (size_t)(kt) * 64;                               \
        cp16(so + sdst,           gK + koK);                                \
        cp16(so + sdst + 16,      gK + koK + 8);                            \
        cp16(so + SV + sdst,      gV + koV);                                \
        cp16(so + SV + sdst + 16, gV + koV + 8);                            \
        if (tid < 16) cp16(so + SLB + tid * 16, gLB + (kt) * 64 + tid * 4); \
        CP_COMMIT();                                                       \
    } while (0)

    AISSUE(0, 0);   // Q joins group 0
    AISSUE(1, 1);

    const uint32_t frow = lane & 15;
    const uint32_t fkb  = ((lane >> 4) & 1) * 16;
    const uint32_t qBase = (wid * 16 + frow) * QROW + fkb;
    uint32_t qhf[4][4];

    float o[8][4];
#pragma unroll
    for (int j = 0; j < 8; j++)
#pragma unroll
        for (int q = 0; q < 4; q++) o[j][q] = 0.f;
    float m0 = -1e30f, m1 = -1e30f, l0 = 0.f, l1 = 0.f;

    const int NT = NKV / 64;
#pragma unroll 1
    for (int kt = 0; kt < NT; kt++) {
        if (kt + 1 < NT) { CP_WAIT(1); } else { CP_WAIT(0); }
        __syncthreads();
        if (kt == 0) {
#pragma unroll
            for (int ks = 0; ks < 4; ks++) ldsm4(qhf[ks], sb + qBase + ks * 32);
        }
        if (kt + 2 < NT) AISSUE((kt + 2) % 3, kt + 2);
        const uint32_t st = sb + SQ_SZ + (kt % 3) * STG_SZ;

        // S = (Qh+Ql) K^T
        float c[8][4];
#pragma unroll
        for (int j = 0; j < 8; j++)
#pragma unroll
            for (int q = 0; q < 4; q++) c[j][q] = 0.f;

#pragma unroll
        for (int ks = 0; ks < 4; ks++) {
            uint32_t ql_[4];
            ldsm4(ql_, sb + SQ_L + qBase + ks * 32);
#pragma unroll
            for (int nb = 0; nb < 4; nb++) {
                uint32_t kf[4];
                ldsm4(kf, st + (nb * 16 + frow) * QROW + fkb + ks * 32);
                mma_h(c[nb * 2], qhf[ks], kf[0], kf[2]);
                mma_h(c[nb * 2], ql_,     kf[0], kf[2]);
                mma_h(c[nb * 2 + 1], qhf[ks], kf[1], kf[3]);
                mma_h(c[nb * 2 + 1], ql_,     kf[1], kf[3]);
            }
        }

        // + log multiplicity
        const float* lbs = (const float*)(sm + SQ_SZ + (kt % 3) * STG_SZ + SLB);
#pragma unroll
        for (int j = 0; j < 8; j++) {
            float2 lb2 = *(const float2*)(lbs + j * 8 + (lane & 3) * 2);
            c[j][0] += lb2.x; c[j][1] += lb2.y;
            c[j][2] += lb2.x; c[j][3] += lb2.y;
        }

        // online softmax
        float rm0 = -1e30f, rm1 = -1e30f;
#pragma unroll
        for (int j = 0; j < 8; j++) {
            rm0 = fmaxf(rm0, fmaxf(c[j][0], c[j][1]));
            rm1 = fmaxf(rm1, fmaxf(c[j][2], c[j][3]));
        }
#pragma unroll
        for (int off = 1; off < 4; off <<= 1) {
            rm0 = fmaxf(rm0, __shfl_xor_sync(0xffffffffu, rm0, off));
            rm1 = fmaxf(rm1, __shfl_xor_sync(0xffffffffu, rm1, off));
        }
        const float mn0 = fmaxf(m0, rm0), mn1 = fmaxf(m1, rm1);
        const float al0 = __expf(m0 - mn0), al1 = __expf(m1 - mn1);
        float rs0 = 0.f, rs1 = 0.f;
#pragma unroll
        for (int j = 0; j < 8; j++) {
            c[j][0] = __expf(c[j][0] - mn0); rs0 += c[j][0];
            c[j][1] = __expf(c[j][1] - mn0); rs0 += c[j][1];
            c[j][2] = __expf(c[j][2] - mn1); rs1 += c[j][2];
            c[j][3] = __expf(c[j][3] - mn1); rs1 += c[j][3];
        }
#pragma unroll
        for (int off = 1; off < 4; off <<= 1) {
            rs0 += __shfl_xor_sync(0xffffffffu, rs0, off);
            rs1 += __shfl_xor_sync(0xffffffffu, rs1, off);
        }
        l0 = l0 * al0 + rs0;  m0 = mn0;
        l1 = l1 * al1 + rs1;  m1 = mn1;
#pragma unroll
        for (int j = 0; j < 8; j++) {
            o[j][0] *= al0; o[j][1] *= al0;
            o[j][2] *= al1; o[j][3] *= al1;
        }

        // O += (Ph+Pl) V
#pragma unroll
        for (int kk = 0; kk < 4; kk++) {
            const int j0 = 2 * kk, j1 = 2 * kk + 1;
            float ph[8], pl[8];
            const float pv[8] = {c[j0][0], c[j0][1], c[j0][2], c[j0][3],
                                 c[j1][0], c[j1][1], c[j1][2], c[j1][3]};
#pragma unroll
            for (int q = 0; q < 8; q++) {
                ph[q] = __half2float(__float2half_rn(pv[q]));
                pl[q] = pv[q] - ph[q];
            }
            uint32_t ah[4], al_[4];
            ah[0] = packh(ph[0], ph[1]);  ah[1] = packh(ph[2], ph[3]);
            ah[2] = packh(ph[4], ph[5]);  ah[3] = packh(ph[6], ph[7]);
            al_[0] = packh(pl[0], pl[1]); al_[1] = packh(pl[2], pl[3]);
            al_[2] = packh(pl[4], pl[5]); al_[3] = packh(pl[6], pl[7]);
#pragma unroll
            for (int nb = 0; nb < 4; nb++) {
                uint32_t vh[4];
                ldsm4(vh, st + SV + (nb * 16 + frow) * QROW + fkb + kk * 32);
                mma_h(o[nb * 2], ah,  vh[0], vh[2]);
                mma_h(o[nb * 2], al_, vh[0], vh[2]);
                mma_h(o[nb * 2 + 1], ah,  vh[1], vh[3]);
                mma_h(o[nb * 2 + 1], al_, vh[1], vh[3]);
            }
        }
    }

    // epilogue: normalize, write fp16 hi/lo
    const float inv0 = 1.f / l0, inv1 = 1.f / l1;
    const int r0 = qt * 128 + wid * 16 + (lane >> 2);
    const int cc0 = h * HD + (lane & 3) * 2;
#pragma unroll
    for (int j = 0; j < 8; j++) {
        const int col = cc0 + j * 8;
        {
            float v0 = o[j][0] * inv0, v1 = o[j][1] * inv0;
            float h0 = __half2float(__float2half_rn(v0));
            float h1 = __half2float(__float2half_rn(v1));
            size_t idx = ((size_t)(b * NQV + r0)) * EMBED + col;
            *(uint32_t*)(Oh + idx) = packh(h0, h1);
            *(uint32_t*)(Ol + idx) = packh(v0 - h0, v1 - h1);
        }
        {
            float v0 = o[j][2] * inv1, v1 = o[j][3] * inv1;
            float h0 = __half2float(__float2half_rn(v0));
            float h1 = __half2float(__float2half_rn(v1));
            size_t idx = ((size_t)(b * NQV + r0 + 8)) * EMBED + col;
            *(uint32_t*)(Oh + idx) = packh(h0, h1);
            *(uint32_t*)(Ol + idx) = packh(v0 - h0, v1 - h1);
        }
    }
#undef AISSUE
}

// ---------------------------------------------------------------------------
extern "C" void kernel_launch(void* const* d_in, const int* in_sizes, int n_in,
                              void* d_out, int out_size)
{
    const float* query = (const float*)d_in[0];
    const float* key   = (const float*)d_in[1];
    const float* value = (const float*)d_in[2];
    const float* mult  = (const float*)d_in[3];
    const float* wq_w  = (const float*)d_in[4];
    const float* wq_b  = (const float*)d_in[5];
    const float* wk_w  = (const float*)d_in[6];
    const float* wk_b  = (const float*)d_in[7];
    const float* wv_w  = (const float*)d_in[8];
    const float* wv_b  = (const float*)d_in[9];
    const float* wo_w  = (const float*)d_in[10];
    const float* wo_b  = (const float*)d_in[11];
    float* out = (float*)d_out;

    float* glb;  cudaGetSymbolAddress((void**)&glb, g_lb);
    __half *q16,*k16,*v16h,*v16l;
    __half *wq16,*wk16,*wv16,*wo16;
    __half *qs16h,*qs16l,*ks16,*vt16,*ao16h,*ao16l;
    cudaGetSymbolAddress((void**)&q16, g_q16);
    cudaGetSymbolAddress((void**)&k16, g_k16);
    cudaGetSymbolAddress((void**)&v16h, g_v16h); cudaGetSymbolAddress((void**)&v16l, g_v16l);
    cudaGetSymbolAddress((void**)&wq16, g_wq16); cudaGetSymbolAddress((void**)&wk16, g_wk16);
    cudaGetSymbolAddress((void**)&wv16, g_wv16); cudaGetSymbolAddress((void**)&wo16, g_wo16);
    cudaGetSymbolAddress((void**)&qs16h, g_qs16h); cudaGetSymbolAddress((void**)&qs16l, g_qs16l);
    cudaGetSymbolAddress((void**)&ks16, g_ks16);
    cudaGetSymbolAddress((void**)&vt16, g_vt16);
    cudaGetSymbolAddress((void**)&ao16h, g_ao16h); cudaGetSymbolAddress((void**)&ao16l, g_ao16l);

    cudaFuncSetAttribute((void*)gemm_f2<0,1>, cudaFuncAttributeMaxDynamicSharedMemorySize, F2_SMEM);
    cudaFuncSetAttribute((void*)gemm_f2<3,1>, cudaFuncAttributeMaxDynamicSharedMemorySize, F2_SMEM);
    cudaFuncSetAttribute((void*)gemm_f2<4,0>, cudaFuncAttributeMaxDynamicSharedMemorySize, F2_SMEM);
    cudaFuncSetAttribute((void*)gemm_f2<5,0>, cudaFuncAttributeMaxDynamicSharedMemorySize, F2_SMEM);
    cudaFuncSetAttribute(attn_hmma, cudaFuncAttributeMaxDynamicSharedMemorySize, ASMEM);

    const int MQ = BATCH * NQV;   // 4096
    const int MK = BATCH * NKV;   // 8192

    // 0: inputs -> fp16 (q,k single; v hi/lo)
    cvt_inputs<<<20480, 256>>>(query, key, value, q16, k16, v16h, v16l);
    // 1: weights -> fp16
    cvt_weights<<<4096, 256>>>(wq_w, wk_w, wv_w, wo_w, wq16, wk16, wv16, wo16);
    // 2: log multiplicities
    log_mult<<<MK / 256, 256>>>(mult, glb);
    // 3 (ncu slot): V proj (2-term) -> transposed fp16 V^T
    gemm_f2<3,1><<<dim3(EMBED / 256, MK / 128), 256, F2_SMEM>>>(
        v16h, v16l, wv16, wv_b, nullptr, vt16, nullptr, nullptr, MK, EMBED, EMBED);
    // 4: Q proj (single-term) -> scaled fp16 hi/lo
    gemm_f2<4,0><<<dim3(EMBED / 256, MQ / 128), 256, F2_SMEM>>>(
        q16, nullptr, wq16, wq_b, nullptr, nullptr, qs16h, qs16l, MQ, EMBED, EMBED);
    // 5: K proj (single-term) -> fp16 single
    gemm_f2<5,0><<<dim3(EMBED / 256, MK / 128), 256, F2_SMEM>>>(
        k16, nullptr, wk16, wk_b, nullptr, nullptr, ks16, nullptr, MK, EMBED, EMBED);
    // 6: attention (round-11 exact)
    attn_hmma<<<dim3(NQV / 128, NH, BATCH), 256, ASMEM>>>(
        qs16h, qs16l, ks16, vt16, glb, ao16h, ao16l);
    // 7: O proj (2-term) -> fp32 out
    gemm_f2<0,1><<<dim3(EMBED / 256, MQ / 128), 256, F2_SMEM>>>(
        ao16h, ao16l, wo16, wo_b, out, nullptr, nullptr, nullptr, MQ, EMBED, EMBED);
}